// round 3
// baseline (speedup 1.0000x reference)
#include <cuda_runtime.h>
#include <stdint.h>

#define Bb 4
#define Cc 256
#define Nn 16384
#define Hh 64
#define Ss 10
#define Kq 256

// Output layout (float32, concatenated in tuple order)
#define OFS_Q     0u          // query        (B,3,256)   = 3072
#define OFS_QF    3072u       // query_feats  (B,256,256) = 262144
#define OFS_PRED  265216u     // heatmap_preds (B,10)     = 40
#define OFS_M     265256u     // m            (B,256,N)   = 16777216
#define OFS_G0    17042472u   // grouped0     (B,256,32)  = 32768
#define OFS_G1    17075240u   // grouped1     (B,256,64)  = 65536

// ------------------- device scratch (allocation-free) -------------------
__device__ float g_P[(size_t)Bb*Nn*Hh];       // 16.8 MB
__device__ float g_hm[(size_t)Bb*Nn*Ss];      // 2.6 MB
__device__ float g_mpre[(size_t)Bb*Cc*Nn];    // 67 MB
__device__ float g_hsum[Hh], g_hsq[Hh], g_hmean[Hh], g_hinv[Hh];
__device__ float g_pred[Bb*Ss];
__device__ int   g_label[Bb];
__device__ float g_msum[Cc], g_msq[Cc], g_mmean[Cc], g_minv[Cc];
__device__ int   g_qidx[Bb*Kq];
__device__ float g_qx[Bb*Kq], g_qy[Bb*Kq], g_qz[Bb*Kq];

__device__ __forceinline__ float gelu_t(float x) {
    // JAX default gelu (approximate=True, tanh form)
    float x3 = x * x * x;
    float t = tanhf(0.7978845608028654f * (x + 0.044715f * x3));
    return 0.5f * x * (1.0f + t);
}

__device__ __forceinline__ uint32_t f2ord(float f) {
    uint32_t u = __float_as_uint(f);
    return (u & 0x80000000u) ? ~u : (u | 0x80000000u);
}

// ------------------- kernels -------------------

__global__ void k_reset() {
    int t = threadIdx.x;
    if (t < Hh)      { g_hsum[t] = 0.0f; g_hsq[t] = 0.0f; }
    if (t < Bb * Ss) { g_pred[t] = 0.0f; }
    if (t < Cc)      { g_msum[t] = 0.0f; g_msq[t] = 0.0f; }
}

// P = x @ w1  where x[b*N+n, c] = feats[b,c,n].  Epilogue: per-column sum/sumsq.
__global__ void __launch_bounds__(256) k_gemm_h(const float* __restrict__ feats,
                                                const float* __restrict__ w1) {
    __shared__ float As[32][128];   // [k][n]
    __shared__ float Ws[32][64];    // [k][h]
    __shared__ float csum[64], csq[64];
    int b = blockIdx.y;
    int n0 = blockIdx.x * 128;
    int tid = threadIdx.x, ty = tid >> 4, tx = tid & 15;
    const float* fb = feats + (size_t)b * Cc * Nn;

    float acc[8][4];
#pragma unroll
    for (int r = 0; r < 8; r++)
#pragma unroll
        for (int c = 0; c < 4; c++) acc[r][c] = 0.0f;

    for (int k0 = 0; k0 < Cc; k0 += 32) {
#pragma unroll
        for (int i = 0; i < 4; i++) {
            int t = tid + i * 256; int rw = t >> 5; int c4 = t & 31;
            *(float4*)&As[rw][c4 * 4] =
                *(const float4*)&fb[(size_t)(k0 + rw) * Nn + n0 + c4 * 4];
        }
#pragma unroll
        for (int i = 0; i < 2; i++) {
            int t = tid + i * 256; int rw = t >> 4; int c4 = t & 15;
            *(float4*)&Ws[rw][c4 * 4] =
                *(const float4*)&w1[(size_t)(k0 + rw) * Hh + c4 * 4];
        }
        __syncthreads();
#pragma unroll
        for (int kk = 0; kk < 32; kk++) {
            float4 a0 = *(float4*)&As[kk][ty * 8];
            float4 a1 = *(float4*)&As[kk][ty * 8 + 4];
            float4 bb = *(float4*)&Ws[kk][tx * 4];
            float ar[8] = {a0.x, a0.y, a0.z, a0.w, a1.x, a1.y, a1.z, a1.w};
            float br[4] = {bb.x, bb.y, bb.z, bb.w};
#pragma unroll
            for (int r = 0; r < 8; r++)
#pragma unroll
                for (int c = 0; c < 4; c++) acc[r][c] += ar[r] * br[c];
        }
        __syncthreads();
    }

    if (tid < 64) { csum[tid] = 0.0f; csq[tid] = 0.0f; }
    __syncthreads();

    size_t rbase = ((size_t)b * Nn + n0 + ty * 8) * Hh + tx * 4;
#pragma unroll
    for (int r = 0; r < 8; r++) {
        *(float4*)&g_P[rbase + (size_t)r * Hh] =
            make_float4(acc[r][0], acc[r][1], acc[r][2], acc[r][3]);
    }
#pragma unroll
    for (int c = 0; c < 4; c++) {
        float s = 0.0f, q = 0.0f;
#pragma unroll
        for (int r = 0; r < 8; r++) { s += acc[r][c]; q += acc[r][c] * acc[r][c]; }
        atomicAdd(&csum[tx * 4 + c], s);
        atomicAdd(&csq [tx * 4 + c], q);
    }
    __syncthreads();
    if (tid < 64) {
        atomicAdd(&g_hsum[tid], csum[tid]);
        atomicAdd(&g_hsq [tid], csq [tid]);
    }
}

__global__ void k_finh() {
    int t = threadIdx.x;
    if (t < Hh) {
        float inv_n = 1.0f / (float)(Bb * Nn);
        float m = g_hsum[t] * inv_n;
        float v = g_hsq[t] * inv_n - m * m;
        g_hmean[t] = m;
        g_hinv[t]  = rsqrtf(v + 1e-5f);
    }
}

// heatmap = gelu(BN(P)) @ w2 ; accumulate per-(batch,class) sums
__global__ void __launch_bounds__(256) k_heat(const float* __restrict__ g1,
                                              const float* __restrict__ b1,
                                              const float* __restrict__ w2) {
    __shared__ float w2s[Hh * Ss];
    __shared__ float smn[Hh], siv[Hh], sga[Hh], sbe[Hh];
    __shared__ float sp[Ss];
    int tid = threadIdx.x;
    if (tid < Hh) {
        smn[tid] = g_hmean[tid]; siv[tid] = g_hinv[tid];
        sga[tid] = g1[tid];      sbe[tid] = b1[tid];
    }
    for (int i = tid; i < Hh * Ss; i += 256) w2s[i] = w2[i];
    if (tid < Ss) sp[tid] = 0.0f;
    __syncthreads();

    int r = blockIdx.x * 256 + tid;
    int b = r >> 14;
    const float* pr = &g_P[(size_t)r * Hh];
    float o[Ss];
#pragma unroll
    for (int s = 0; s < Ss; s++) o[s] = 0.0f;
#pragma unroll 4
    for (int j = 0; j < Hh; j++) {
        float h = gelu_t((pr[j] - smn[j]) * siv[j] * sga[j] + sbe[j]);
#pragma unroll
        for (int s = 0; s < Ss; s++) o[s] += h * w2s[j * Ss + s];
    }
#pragma unroll
    for (int s = 0; s < Ss; s++) {
        g_hm[(size_t)r * Ss + s] = o[s];
        atomicAdd(&sp[s], o[s]);
    }
    __syncthreads();
    if (tid < Ss) atomicAdd(&g_pred[b * Ss + tid], sp[tid]);
}

__global__ void k_finpred(float* __restrict__ out) {
    __shared__ float p[Bb * Ss];
    int t = threadIdx.x;
    if (t < Bb * Ss) {
        float v = g_pred[t] * (1.0f / (float)Nn);
        p[t] = v;
        out[OFS_PRED + t] = v;
    }
    __syncthreads();
    if (t < Bb) {
        int best = 0; float bv = p[t * Ss];
        for (int s = 1; s < Ss; s++) {
            float v = p[t * Ss + s];
            if (v > bv) { bv = v; best = s; }
        }
        g_label[t] = best;
    }
}

// Exact top-256 by (value desc, index asc): radix select + bitonic sort.
__global__ void __launch_bounds__(256) k_select(const float* __restrict__ points,
                                                float* __restrict__ out) {
    extern __shared__ uint32_t dyn[];
    uint32_t* u   = dyn;             // 16384 keys
    uint32_t* tie = dyn + Nn;        // 16384 tie indices (worst case)
    __shared__ uint32_t hist[256];
    __shared__ unsigned long long sel[256];
    __shared__ uint32_t s_prefix, s_rem, s_cntG, s_cntE;

    int tid = threadIdx.x;
    int b = blockIdx.x;
    int lab = g_label[b];

    for (int n = tid; n < Nn; n += 256)
        u[n] = f2ord(g_hm[((size_t)(b * Nn + n)) * Ss + lab]);
    if (tid == 0) { s_prefix = 0u; s_rem = Kq; }
    __syncthreads();

    for (int shift = 24; shift >= 0; shift -= 8) {
        hist[tid] = 0u;
        __syncthreads();
        uint32_t pref = s_prefix;
        for (int n = tid; n < Nn; n += 256) {
            uint32_t uu = u[n];
            bool ok = (shift == 24) || ((uu >> (shift + 8)) == (pref >> (shift + 8)));
            if (ok) atomicAdd(&hist[(uu >> shift) & 255u], 1u);
        }
        __syncthreads();
        if (tid == 0) {
            uint32_t acc = 0, rem = s_rem; int chosen = 0;
            for (int bin = 255; bin >= 0; --bin) {
                uint32_t c = hist[bin];
                if (acc + c >= rem) { chosen = bin; break; }
                acc += c;
            }
            s_rem = rem - acc;
            s_prefix = pref | ((uint32_t)chosen << shift);
        }
        __syncthreads();
    }

    uint32_t T = s_prefix;
    uint32_t need = s_rem;
    if (tid == 0) { s_cntG = 0u; s_cntE = 0u; }
    __syncthreads();
    for (int n = tid; n < Nn; n += 256) {
        uint32_t uu = u[n];
        if (uu > T) {
            uint32_t p = atomicAdd(&s_cntG, 1u);
            sel[p] = (((unsigned long long)(~uu)) << 32) | (uint32_t)n;
        } else if (uu == T) {
            uint32_t p = atomicAdd(&s_cntE, 1u);
            tie[p] = (uint32_t)n;
        }
    }
    __syncthreads();
    uint32_t cG = s_cntG, cE = s_cntE;

    if (cE > need) {  // pathological ties: full ascending sort of tie indices
        for (int i = tid; i < Nn; i += 256)
            if (i >= (int)cE) tie[i] = 0xFFFFFFFFu;
        __syncthreads();
        for (int k = 2; k <= Nn; k <<= 1)
            for (int j = k >> 1; j > 0; j >>= 1) {
                for (int i = tid; i < Nn; i += 256) {
                    int ixj = i ^ j;
                    if (ixj > i) {
                        uint32_t a = tie[i], c = tie[ixj];
                        bool up = ((i & k) == 0);
                        if ((a > c) == up) { tie[i] = c; tie[ixj] = a; }
                    }
                }
                __syncthreads();
            }
    }
    for (uint32_t i = tid; i < need; i += 256)
        sel[cG + i] = (((unsigned long long)(~T)) << 32) | tie[i];
    __syncthreads();

    // bitonic sort 256 keys ascending (= value desc, index asc)
    for (int k = 2; k <= 256; k <<= 1)
        for (int j = k >> 1; j > 0; j >>= 1) {
            int i = tid, ixj = i ^ j;
            if (ixj > i) {
                unsigned long long a = sel[i], c = sel[ixj];
                bool up = ((i & k) == 0);
                if ((a > c) == up) { sel[i] = c; sel[ixj] = a; }
            }
            __syncthreads();
        }

    int k = tid;
    uint32_t idx = (uint32_t)(sel[k] & 0xFFFFFFFFu);
    g_qidx[b * Kq + k] = (int)idx;
    const float* pb = points + (size_t)b * 3 * Nn;
    float px = pb[idx], py = pb[Nn + idx], pz = pb[2 * Nn + idx];
    out[OFS_Q + (size_t)b * 768 + k]       = px;
    out[OFS_Q + (size_t)b * 768 + 256 + k] = py;
    out[OFS_Q + (size_t)b * 768 + 512 + k] = pz;
    g_qx[b * Kq + k] = px; g_qy[b * Kq + k] = py; g_qz[b * Kq + k] = pz;
}

__global__ void k_qfeats(const float* __restrict__ feats, float* __restrict__ out) {
    int bid = blockIdx.x;
    int b = bid >> 8, c = bid & 255, k = threadIdx.x;
    int idx = g_qidx[b * Kq + k];
    out[OFS_QF + ((size_t)(b * Cc + c)) * Kq + k] =
        __ldg(&feats[(size_t)b * Cc * Nn + (size_t)c * Nn + idx]);
}

// m_pre[b,d,n] = sum_c wm[c,d] * feats[b,c,n].  Epilogue: per-d sum/sumsq.
__global__ void __launch_bounds__(256) k_gemm_m(const float* __restrict__ feats,
                                                const float* __restrict__ wm) {
    __shared__ float Ws[16][128];   // [c][d]
    __shared__ float Fs[16][128];   // [c][n]
    __shared__ float ssum[128], ssq[128];
    int b = blockIdx.z;
    int d0 = blockIdx.y * 128;
    int n0 = blockIdx.x * 128;
    int tid = threadIdx.x, ty = tid >> 4, tx = tid & 15;
    const float* fb = feats + (size_t)b * Cc * Nn;

    if (tid < 128) { ssum[tid] = 0.0f; ssq[tid] = 0.0f; }

    float acc[8][8];
#pragma unroll
    for (int r = 0; r < 8; r++)
#pragma unroll
        for (int c = 0; c < 8; c++) acc[r][c] = 0.0f;

    for (int k0 = 0; k0 < Cc; k0 += 16) {
#pragma unroll
        for (int i = 0; i < 2; i++) {
            int t = tid + i * 256; int rw = t >> 5; int c4 = t & 31;
            *(float4*)&Ws[rw][c4 * 4] =
                *(const float4*)&wm[(size_t)(k0 + rw) * Cc + d0 + c4 * 4];
            *(float4*)&Fs[rw][c4 * 4] =
                *(const float4*)&fb[(size_t)(k0 + rw) * Nn + n0 + c4 * 4];
        }
        __syncthreads();
#pragma unroll
        for (int kk = 0; kk < 16; kk++) {
            float a[8], bv[8];
            *(float4*)&a[0]  = *(float4*)&Ws[kk][ty * 8];
            *(float4*)&a[4]  = *(float4*)&Ws[kk][ty * 8 + 4];
            *(float4*)&bv[0] = *(float4*)&Fs[kk][tx * 8];
            *(float4*)&bv[4] = *(float4*)&Fs[kk][tx * 8 + 4];
#pragma unroll
            for (int r = 0; r < 8; r++)
#pragma unroll
                for (int c = 0; c < 8; c++) acc[r][c] += a[r] * bv[c];
        }
        __syncthreads();
    }

    size_t obase = ((size_t)(b * Cc + d0 + ty * 8)) * Nn + n0 + tx * 8;
#pragma unroll
    for (int r = 0; r < 8; r++) {
        *(float4*)&g_mpre[obase + (size_t)r * Nn] =
            make_float4(acc[r][0], acc[r][1], acc[r][2], acc[r][3]);
        *(float4*)&g_mpre[obase + (size_t)r * Nn + 4] =
            make_float4(acc[r][4], acc[r][5], acc[r][6], acc[r][7]);
        float s = 0.0f, q = 0.0f;
#pragma unroll
        for (int c = 0; c < 8; c++) { s += acc[r][c]; q += acc[r][c] * acc[r][c]; }
        atomicAdd(&ssum[ty * 8 + r], s);
        atomicAdd(&ssq [ty * 8 + r], q);
    }
    __syncthreads();
    if (tid < 128) {
        atomicAdd(&g_msum[d0 + tid], ssum[tid]);
        atomicAdd(&g_msq [d0 + tid], ssq [tid]);
    }
}

__global__ void k_finm() {
    int t = threadIdx.x;
    if (t < Cc) {
        float inv_n = 1.0f / (float)(Bb * Nn);
        float m = g_msum[t] * inv_n;
        float v = g_msq[t] * inv_n - m * m;
        g_mmean[t] = m;
        g_minv[t]  = rsqrtf(v + 1e-5f);
    }
}

__global__ void __launch_bounds__(256) k_bnapply(const float* __restrict__ gm,
                                                 const float* __restrict__ bm,
                                                 float* __restrict__ out) {
    size_t i4 = (size_t)blockIdx.x * 256 + threadIdx.x;   // over 4194304
    size_t i = i4 * 4;
    int d = (int)((i >> 14) & 255u);
    float mean = g_mmean[d], inv = g_minv[d], ga = gm[d], be = bm[d];
    float4 v = *(const float4*)&g_mpre[i];
    v.x = gelu_t((v.x - mean) * inv * ga + be);
    v.y = gelu_t((v.y - mean) * inv * ga + be);
    v.z = gelu_t((v.z - mean) * inv * ga + be);
    v.w = gelu_t((v.w - mean) * inv * ga + be);
    *(float4*)&out[OFS_M + i] = v;
}

__global__ void k_ballq(const float* __restrict__ points, float* __restrict__ out) {
    int gid = blockIdx.x * blockDim.x + threadIdx.x;
    int w = gid >> 5, lane = gid & 31;
    if (w >= Bb * Kq) return;
    int b = w >> 8;
    float qx = g_qx[w], qy = g_qy[w], qz = g_qz[w];
    const float* px = points + (size_t)b * 3 * Nn;
    const float* py = px + Nn;
    const float* pz = px + 2 * Nn;
    float* o0 = out + OFS_G0 + (size_t)w * 32;
    float* o1 = out + OFS_G1 + (size_t)w * 64;
    int cnt0 = 0, cnt1 = 0, first0 = -1, first1 = -1;
    const float r0sq = 0.04f, r1sq = 0.16f;   // f32(rad*rad in f64)

    for (int base = 0; base < Nn; base += 32) {
        int n = base + lane;
        float dx = __fadd_rn(px[n], -qx);
        float dy = __fadd_rn(py[n], -qy);
        float dz = __fadd_rn(pz[n], -qz);
        float d2 = __fadd_rn(__fadd_rn(__fmul_rn(dx, dx), __fmul_rn(dy, dy)),
                             __fmul_rn(dz, dz));
        bool in1 = (d2 <= r1sq);
        bool in0 = (d2 <= r0sq);
        unsigned m1 = __ballot_sync(0xffffffffu, in1);
        unsigned m0 = __ballot_sync(0xffffffffu, in0);
        if (m1) {
            if (first1 < 0) first1 = base + __ffs(m1) - 1;
            if (cnt1 < 64) {
                if (in1) {
                    int slot = cnt1 + __popc(m1 & ((1u << lane) - 1u));
                    if (slot < 64) o1[slot] = (float)n;
                }
                cnt1 += __popc(m1);
                if (cnt1 > 64) cnt1 = 64;
            }
        }
        if (m0) {
            if (first0 < 0) first0 = base + __ffs(m0) - 1;
            if (cnt0 < 32) {
                if (in0) {
                    int slot = cnt0 + __popc(m0 & ((1u << lane) - 1u));
                    if (slot < 32) o0[slot] = (float)n;
                }
                cnt0 += __popc(m0);
                if (cnt0 > 32) cnt0 = 32;
            }
        }
        if (cnt0 >= 32 && cnt1 >= 64) break;
    }
    if (first1 < 0) first1 = Nn - 1;
    if (first0 < 0) first0 = Nn - 1;
    for (int s = cnt1 + lane; s < 64; s += 32) o1[s] = (float)first1;
    for (int s = cnt0 + lane; s < 32; s += 32) o0[s] = (float)first0;
}

// ------------------- host -------------------
extern "C" void kernel_launch(void* const* d_in, const int* in_sizes, int n_in,
                              void* d_out, int out_size) {
    const float* points = (const float*)d_in[0];
    const float* feats  = (const float*)d_in[1];
    const float* w1     = (const float*)d_in[2];
    const float* g1     = (const float*)d_in[3];
    const float* b1     = (const float*)d_in[4];
    const float* w2     = (const float*)d_in[5];
    const float* wm     = (const float*)d_in[6];
    const float* gm     = (const float*)d_in[7];
    const float* bm     = (const float*)d_in[8];
    float* out = (float*)d_out;

    cudaFuncSetAttribute(k_select, cudaFuncAttributeMaxDynamicSharedMemorySize,
                         2 * Nn * (int)sizeof(uint32_t));

    k_reset<<<1, 256>>>();
    k_gemm_h<<<dim3(Nn / 128, Bb), 256>>>(feats, w1);
    k_finh<<<1, 64>>>();
    k_heat<<<(Bb * Nn) / 256, 256>>>(g1, b1, w2);
    k_finpred<<<1, 64>>>(out);
    k_select<<<Bb, 256, 2 * Nn * sizeof(uint32_t)>>>(points, out);
    k_qfeats<<<Bb * Cc, Kq>>>(feats, out);
    k_gemm_m<<<dim3(Nn / 128, Cc / 128, Bb), 256>>>(feats, wm);
    k_finm<<<1, 256>>>();
    k_bnapply<<<(Bb * Cc * Nn) / (256 * 4), 256>>>(gm, bm, out);
    k_ballq<<<(Bb * Kq * 32) / 128, 128>>>(points, out);
}

// round 7
// speedup vs baseline: 1.1819x; 1.1819x over previous
#include <cuda_runtime.h>
#include <cuda_bf16.h>
#include <stdint.h>

#define Bb 4
#define Cc 256
#define Nn 16384
#define Hh 64
#define Ss 10
#define Kq 256
#define BN (Bb*Nn)

// Output layout (float32, concatenated in tuple order)
#define OFS_Q     0u
#define OFS_QF    3072u
#define OFS_PRED  265216u
#define OFS_M     265256u
#define OFS_G0    17042472u
#define OFS_G1    17075240u

// ------------------- device scratch (allocation-free) -------------------
__device__ float g_P[(size_t)Hh*BN];          // transposed: [h][row]
__device__ float g_hm[(size_t)Bb*Nn*Ss];
__device__ float g_mpre[(size_t)Bb*Cc*Nn];    // 67 MB
__device__ float g_hsum[Hh], g_hsq[Hh], g_hmean[Hh], g_hinv[Hh];
__device__ float g_pred[Bb*Ss];
__device__ int   g_label[Bb];
__device__ float g_msum[Cc], g_msq[Cc], g_mmean[Cc], g_minv[Cc];
__device__ int   g_qidx[Bb*Kq];
__device__ float g_qx[Bb*Kq], g_qy[Bb*Kq], g_qz[Bb*Kq];
// wm^T bf16 hi/lo, plain row-major [d][c]
__device__ __nv_bfloat16 g_wmTh[Cc*Cc];
__device__ __nv_bfloat16 g_wmTl[Cc*Cc];

__device__ __forceinline__ float gelu_t(float x) {
    float x3 = x * x * x;
    float t = tanhf(0.7978845608028654f * (x + 0.044715f * x3));
    return 0.5f * x * (1.0f + t);
}
__device__ __forceinline__ uint32_t f2ord(float f) {
    uint32_t u = __float_as_uint(f);
    return (u & 0x80000000u) ? ~u : (u | 0x80000000u);
}
__device__ __forceinline__ uint32_t smem_u32(const void* p) {
    uint32_t a;
    asm("{ .reg .u64 t; cvta.to.shared.u64 t, %1; cvt.u32.u64 %0, t; }"
        : "=r"(a) : "l"(p));
    return a;
}
__device__ __forceinline__ void ldsm_x4(uint32_t* r, uint32_t addr) {
    asm volatile("ldmatrix.sync.aligned.m8n8.x4.shared.b16 {%0,%1,%2,%3}, [%4];"
                 : "=r"(r[0]), "=r"(r[1]), "=r"(r[2]), "=r"(r[3]) : "r"(addr));
}
__device__ __forceinline__ void ldsm_x4t(uint32_t* r, uint32_t addr) {
    asm volatile("ldmatrix.sync.aligned.m8n8.x4.trans.shared.b16 {%0,%1,%2,%3}, [%4];"
                 : "=r"(r[0]), "=r"(r[1]), "=r"(r[2]), "=r"(r[3]) : "r"(addr));
}
__device__ __forceinline__ void mma16816(float* d, const uint32_t* a, const uint32_t* b) {
    asm volatile(
        "mma.sync.aligned.m16n8k16.row.col.f32.bf16.bf16.f32 "
        "{%0,%1,%2,%3}, {%4,%5,%6,%7}, {%8,%9}, {%0,%1,%2,%3};"
        : "+f"(d[0]), "+f"(d[1]), "+f"(d[2]), "+f"(d[3])
        : "r"(a[0]), "r"(a[1]), "r"(a[2]), "r"(a[3]), "r"(b[0]), "r"(b[1]));
}

// ------------------- kernels -------------------

__global__ void k_reset() {
    int t = threadIdx.x;
    if (t < Hh)      { g_hsum[t] = 0.0f; g_hsq[t] = 0.0f; }
    if (t < Bb * Ss) { g_pred[t] = 0.0f; }
    if (t < Cc)      { g_msum[t] = 0.0f; g_msq[t] = 0.0f; }
}

// g_wmT[d][c] = wm[c][d], bf16 hi/lo split
__global__ void k_prep_wm(const float* __restrict__ wm) {
    int idx = blockIdx.x * blockDim.x + threadIdx.x;
    for (int i = idx; i < Cc * Cc; i += gridDim.x * blockDim.x) {
        int d = i >> 8, c = i & 255;
        float v = wm[(size_t)c * Cc + d];
        __nv_bfloat16 hi = __float2bfloat16(v);
        __nv_bfloat16 lo = __float2bfloat16(__fsub_rn(v, __bfloat162float(hi)));
        g_wmTh[i] = hi;
        g_wmTl[i] = lo;
    }
}

// P^T = (x @ w1)^T stored [h][row].  Epilogue: per-column sum/sumsq.
__global__ void __launch_bounds__(256) k_gemm_h(const float* __restrict__ feats,
                                                const float* __restrict__ w1) {
    __shared__ float As[32][128];
    __shared__ float Ws[32][64];
    __shared__ float csum[64], csq[64];
    int b = blockIdx.y;
    int n0 = blockIdx.x * 128;
    int tid = threadIdx.x, ty = tid >> 4, tx = tid & 15;
    const float* fb = feats + (size_t)b * Cc * Nn;

    float acc[8][4];
#pragma unroll
    for (int r = 0; r < 8; r++)
#pragma unroll
        for (int c = 0; c < 4; c++) acc[r][c] = 0.0f;

    for (int k0 = 0; k0 < Cc; k0 += 32) {
#pragma unroll
        for (int i = 0; i < 4; i++) {
            int t = tid + i * 256; int rw = t >> 5; int c4 = t & 31;
            *(float4*)&As[rw][c4 * 4] =
                *(const float4*)&fb[(size_t)(k0 + rw) * Nn + n0 + c4 * 4];
        }
#pragma unroll
        for (int i = 0; i < 2; i++) {
            int t = tid + i * 256; int rw = t >> 4; int c4 = t & 15;
            *(float4*)&Ws[rw][c4 * 4] =
                *(const float4*)&w1[(size_t)(k0 + rw) * Hh + c4 * 4];
        }
        __syncthreads();
#pragma unroll
        for (int kk = 0; kk < 32; kk++) {
            float4 a0 = *(float4*)&As[kk][ty * 8];
            float4 a1 = *(float4*)&As[kk][ty * 8 + 4];
            float4 bb = *(float4*)&Ws[kk][tx * 4];
            float ar[8] = {a0.x, a0.y, a0.z, a0.w, a1.x, a1.y, a1.z, a1.w};
            float br[4] = {bb.x, bb.y, bb.z, bb.w};
#pragma unroll
            for (int r = 0; r < 8; r++)
#pragma unroll
                for (int c = 0; c < 4; c++) acc[r][c] += ar[r] * br[c];
        }
        __syncthreads();
    }

    if (tid < 64) { csum[tid] = 0.0f; csq[tid] = 0.0f; }
    __syncthreads();

    size_t rowbase = (size_t)b * Nn + n0 + ty * 8;
#pragma unroll
    for (int c = 0; c < 4; c++) {
        int h = tx * 4 + c;
        *(float4*)&g_P[(size_t)h * BN + rowbase] =
            make_float4(acc[0][c], acc[1][c], acc[2][c], acc[3][c]);
        *(float4*)&g_P[(size_t)h * BN + rowbase + 4] =
            make_float4(acc[4][c], acc[5][c], acc[6][c], acc[7][c]);
        float s = 0.0f, q = 0.0f;
#pragma unroll
        for (int r = 0; r < 8; r++) { s += acc[r][c]; q += acc[r][c] * acc[r][c]; }
        atomicAdd(&csum[h], s);
        atomicAdd(&csq [h], q);
    }
    __syncthreads();
    if (tid < 64) {
        atomicAdd(&g_hsum[tid], csum[tid]);
        atomicAdd(&g_hsq [tid], csq [tid]);
    }
}

__global__ void k_finh() {
    int t = threadIdx.x;
    if (t < Hh) {
        float inv_n = 1.0f / (float)BN;
        float m = g_hsum[t] * inv_n;
        float v = g_hsq[t] * inv_n - m * m;
        g_hmean[t] = m;
        g_hinv[t]  = rsqrtf(v + 1e-5f);
    }
}

// heatmap from transposed P: coalesced column reads
__global__ void __launch_bounds__(128) k_heat(const float* __restrict__ g1,
                                              const float* __restrict__ b1,
                                              const float* __restrict__ w2) {
    __shared__ float w2s[Hh * Ss];
    __shared__ float smn[Hh], siv[Hh], sga[Hh], sbe[Hh];
    __shared__ float sp[Ss];
    int tid = threadIdx.x;
    if (tid < Hh) {
        smn[tid] = g_hmean[tid]; siv[tid] = g_hinv[tid];
        sga[tid] = g1[tid];      sbe[tid] = b1[tid];
    }
    for (int i = tid; i < Hh * Ss; i += 128) w2s[i] = w2[i];
    if (tid < Ss) sp[tid] = 0.0f;
    __syncthreads();

    int r = blockIdx.x * 128 + tid;
    int b = r >> 14;
    float o[Ss];
#pragma unroll
    for (int s = 0; s < Ss; s++) o[s] = 0.0f;
#pragma unroll 8
    for (int j = 0; j < Hh; j++) {
        float p = g_P[(size_t)j * BN + r];
        float h = gelu_t((p - smn[j]) * siv[j] * sga[j] + sbe[j]);
#pragma unroll
        for (int s = 0; s < Ss; s++) o[s] += h * w2s[j * Ss + s];
    }
#pragma unroll
    for (int s = 0; s < Ss; s++) {
        g_hm[(size_t)r * Ss + s] = o[s];
        atomicAdd(&sp[s], o[s]);
    }
    __syncthreads();
    if (tid < Ss) atomicAdd(&g_pred[b * Ss + tid], sp[tid]);
}

__global__ void k_finpred(float* __restrict__ out) {
    __shared__ float p[Bb * Ss];
    int t = threadIdx.x;
    if (t < Bb * Ss) {
        float v = g_pred[t] * (1.0f / (float)Nn);
        p[t] = v;
        out[OFS_PRED + t] = v;
    }
    __syncthreads();
    if (t < Bb) {
        int best = 0; float bv = p[t * Ss];
        for (int s = 1; s < Ss; s++) {
            float v = p[t * Ss + s];
            if (v > bv) { bv = v; best = s; }
        }
        g_label[t] = best;
    }
}

// Exact top-256 by (value desc, index asc): radix select + bitonic sort.
__global__ void __launch_bounds__(256) k_select(const float* __restrict__ points,
                                                float* __restrict__ out) {
    extern __shared__ uint32_t dyn[];
    uint32_t* u   = dyn;
    uint32_t* tie = dyn + Nn;
    __shared__ uint32_t hist[256];
    __shared__ unsigned long long sel[256];
    __shared__ uint32_t s_prefix, s_rem, s_cntG, s_cntE;

    int tid = threadIdx.x;
    int b = blockIdx.x;
    int lab = g_label[b];

    for (int n = tid; n < Nn; n += 256)
        u[n] = f2ord(g_hm[((size_t)(b * Nn + n)) * Ss + lab]);
    if (tid == 0) { s_prefix = 0u; s_rem = Kq; }
    __syncthreads();

    for (int shift = 24; shift >= 0; shift -= 8) {
        hist[tid] = 0u;
        __syncthreads();
        uint32_t pref = s_prefix;
        for (int n = tid; n < Nn; n += 256) {
            uint32_t uu = u[n];
            bool ok = (shift == 24) || ((uu >> (shift + 8)) == (pref >> (shift + 8)));
            if (ok) atomicAdd(&hist[(uu >> shift) & 255u], 1u);
        }
        __syncthreads();
        if (tid == 0) {
            uint32_t acc = 0, rem = s_rem; int chosen = 0;
            for (int bin = 255; bin >= 0; --bin) {
                uint32_t c = hist[bin];
                if (acc + c >= rem) { chosen = bin; break; }
                acc += c;
            }
            s_rem = rem - acc;
            s_prefix = pref | ((uint32_t)chosen << shift);
        }
        __syncthreads();
    }

    uint32_t T = s_prefix;
    uint32_t need = s_rem;
    if (tid == 0) { s_cntG = 0u; s_cntE = 0u; }
    __syncthreads();
    for (int n = tid; n < Nn; n += 256) {
        uint32_t uu = u[n];
        if (uu > T) {
            uint32_t p = atomicAdd(&s_cntG, 1u);
            sel[p] = (((unsigned long long)(~uu)) << 32) | (uint32_t)n;
        } else if (uu == T) {
            uint32_t p = atomicAdd(&s_cntE, 1u);
            tie[p] = (uint32_t)n;
        }
    }
    __syncthreads();
    uint32_t cG = s_cntG, cE = s_cntE;

    if (cE > need) {
        for (int i = tid; i < Nn; i += 256)
            if (i >= (int)cE) tie[i] = 0xFFFFFFFFu;
        __syncthreads();
        for (int k = 2; k <= Nn; k <<= 1)
            for (int j = k >> 1; j > 0; j >>= 1) {
                for (int i = tid; i < Nn; i += 256) {
                    int ixj = i ^ j;
                    if (ixj > i) {
                        uint32_t a = tie[i], c = tie[ixj];
                        bool up = ((i & k) == 0);
                        if ((a > c) == up) { tie[i] = c; tie[ixj] = a; }
                    }
                }
                __syncthreads();
            }
    }
    for (uint32_t i = tid; i < need; i += 256)
        sel[cG + i] = (((unsigned long long)(~T)) << 32) | tie[i];
    __syncthreads();

    for (int k = 2; k <= 256; k <<= 1)
        for (int j = k >> 1; j > 0; j >>= 1) {
            int i = tid, ixj = i ^ j;
            if (ixj > i) {
                unsigned long long a = sel[i], c = sel[ixj];
                bool up = ((i & k) == 0);
                if ((a > c) == up) { sel[i] = c; sel[ixj] = a; }
            }
            __syncthreads();
        }

    int k = tid;
    uint32_t idx = (uint32_t)(sel[k] & 0xFFFFFFFFu);
    g_qidx[b * Kq + k] = (int)idx;
    const float* pb = points + (size_t)b * 3 * Nn;
    float px = pb[idx], py = pb[Nn + idx], pz = pb[2 * Nn + idx];
    out[OFS_Q + (size_t)b * 768 + k]       = px;
    out[OFS_Q + (size_t)b * 768 + 256 + k] = py;
    out[OFS_Q + (size_t)b * 768 + 512 + k] = pz;
    g_qx[b * Kq + k] = px; g_qy[b * Kq + k] = py; g_qz[b * Kq + k] = pz;
}

__global__ void k_qfeats(const float* __restrict__ feats, float* __restrict__ out) {
    int bid = blockIdx.x;
    int b = bid >> 8, c = bid & 255, k = threadIdx.x;
    int idx = g_qidx[b * Kq + k];
    out[OFS_QF + ((size_t)(b * Cc + c)) * Kq + k] =
        __ldg(&feats[(size_t)b * Cc * Nn + (size_t)c * Nn + idx]);
}

// ---------- m-GEMM via mma.sync bf16 3-product split ----------
// D[d][n] = sum_c wmT[d][c] * feats[b][c][n]
// CTA: 128 d x 128 n. 8 warps: warp w -> dw = (w/4)*64, nw = (w%4)*32.
// A (wmT) smem: [128 d][40 bf16] (32 used + 8 pad), hi/lo
// B (feats) smem: [32 c][136 bf16] (128 used + 8 pad), hi/lo
#define A_STR 40
#define B_STR 136
__global__ void __launch_bounds__(256) k_gemm_m(const float* __restrict__ feats) {
    __shared__ __align__(16) __nv_bfloat16 sAh[128 * A_STR];
    __shared__ __align__(16) __nv_bfloat16 sAl[128 * A_STR];
    __shared__ __align__(16) __nv_bfloat16 sBh[32 * B_STR];
    __shared__ __align__(16) __nv_bfloat16 sBl[32 * B_STR];

    int tid = threadIdx.x;
    int wid = tid >> 5, lane = tid & 31;
    int b  = blockIdx.z;
    int d0 = blockIdx.y * 128;
    int n0 = blockIdx.x * 128;
    int dw = (wid >> 2) * 64;      // warp d offset in tile
    int nw = (wid & 3) * 32;       // warp n offset in tile
    int lrow = lane & 15, lhi = lane >> 4;
    const float* fb = feats + (size_t)b * Cc * Nn;

    uint32_t aHiB = smem_u32(sAh), aLoB = smem_u32(sAl);
    uint32_t bHiB = smem_u32(sBh), bLoB = smem_u32(sBl);

    float acc[4][4][4];
#pragma unroll
    for (int mt = 0; mt < 4; mt++)
#pragma unroll
        for (int nt = 0; nt < 4; nt++)
#pragma unroll
            for (int r = 0; r < 4; r++) acc[mt][nt][r] = 0.0f;

    const uint32_t* wh = (const uint32_t*)g_wmTh;
    const uint32_t* wl = (const uint32_t*)g_wmTl;
    uint32_t* sAhu = (uint32_t*)sAh;
    uint32_t* sAlu = (uint32_t*)sAl;
    uint32_t* sBhu = (uint32_t*)sBh;
    uint32_t* sBlu = (uint32_t*)sBl;

    for (int kc = 0; kc < 8; kc++) {
        __syncthreads();
        // A: wmT[d0..d0+128][kc*32..+32] hi/lo (uint = 2 bf16)
#pragma unroll
        for (int i = tid; i < 2048; i += 256) {
            int row = i >> 4, cp = i & 15;
            int gi = (d0 + row) * (Cc / 2) + kc * 16 + cp;
            sAhu[row * (A_STR / 2) + cp] = wh[gi];
            sAlu[row * (A_STR / 2) + cp] = wl[gi];
        }
        // B: feats[kc*32..+32][n0..+128] -> bf16 hi/lo
#pragma unroll
        for (int i = tid; i < 2048; i += 256) {
            int crow = i >> 6, np = i & 63;
            float2 f2 = *(const float2*)&fb[(size_t)(kc * 32 + crow) * Nn + n0 + 2 * np];
            __nv_bfloat16 h0 = __float2bfloat16(f2.x);
            __nv_bfloat16 h1 = __float2bfloat16(f2.y);
            __nv_bfloat16 l0 = __float2bfloat16(__fsub_rn(f2.x, __bfloat162float(h0)));
            __nv_bfloat16 l1 = __float2bfloat16(__fsub_rn(f2.y, __bfloat162float(h1)));
            sBhu[crow * (B_STR / 2) + np] =
                ((uint32_t)__bfloat16_as_ushort(h1) << 16) | __bfloat16_as_ushort(h0);
            sBlu[crow * (B_STR / 2) + np] =
                ((uint32_t)__bfloat16_as_ushort(l1) << 16) | __bfloat16_as_ushort(l0);
        }
        __syncthreads();

#pragma unroll
        for (int ks = 0; ks < 2; ks++) {
            uint32_t Afh[4][4], Afl[4][4], Bfh[2][4], Bfl[2][4];
#pragma unroll
            for (int mt = 0; mt < 4; mt++) {
                uint32_t aoff = (uint32_t)((dw + mt * 16 + lrow) * (A_STR * 2) +
                                           ks * 32 + lhi * 16);
                ldsm_x4(Afh[mt], aHiB + aoff);
                ldsm_x4(Afl[mt], aLoB + aoff);
            }
#pragma unroll
            for (int np = 0; np < 2; np++) {
                uint32_t boff = (uint32_t)((ks * 16 + lrow) * (B_STR * 2) +
                                           (nw + np * 16) * 2 + lhi * 16);
                ldsm_x4t(Bfh[np], bHiB + boff);
                ldsm_x4t(Bfl[np], bLoB + boff);
            }
#pragma unroll
            for (int mt = 0; mt < 4; mt++)
#pragma unroll
                for (int nt = 0; nt < 4; nt++) {
                    const uint32_t* bh = &Bfh[nt >> 1][(nt & 1) * 2];
                    const uint32_t* bl = &Bfl[nt >> 1][(nt & 1) * 2];
                    mma16816(acc[mt][nt], Afh[mt], bh);
                    mma16816(acc[mt][nt], Afh[mt], bl);
                    mma16816(acc[mt][nt], Afl[mt], bh);
                }
        }
    }

    // epilogue: D[d][n] -> g_mpre[b][d][n]
    int tg = lane & 3, g = lane >> 2;
#pragma unroll
    for (int mt = 0; mt < 4; mt++) {
        int dr0 = d0 + dw + mt * 16 + g;
#pragma unroll
        for (int nt = 0; nt < 4; nt++) {
            int ncol = n0 + nw + nt * 8 + 2 * tg;
            *(float2*)&g_mpre[((size_t)(b * Cc + dr0)) * Nn + ncol] =
                make_float2(acc[mt][nt][0], acc[mt][nt][1]);
            *(float2*)&g_mpre[((size_t)(b * Cc + dr0 + 8)) * Nn + ncol] =
                make_float2(acc[mt][nt][2], acc[mt][nt][3]);
        }
    }
}

// per-d sum/sumsq over g_mpre (one block per (b,d) row)
__global__ void __launch_bounds__(256) k_mstats() {
    __shared__ float ws[8], wq[8];
    int row = blockIdx.x;
    int tid = threadIdx.x;
    const float4* p = (const float4*)(g_mpre + (size_t)row * Nn);
    float s = 0.0f, q = 0.0f;
    for (int i = tid; i < Nn / 4; i += 256) {
        float4 v = p[i];
        s += v.x + v.y + v.z + v.w;
        q += v.x * v.x + v.y * v.y + v.z * v.z + v.w * v.w;
    }
#pragma unroll
    for (int o = 16; o; o >>= 1) {
        s += __shfl_xor_sync(0xffffffffu, s, o);
        q += __shfl_xor_sync(0xffffffffu, q, o);
    }
    if ((tid & 31) == 0) { ws[tid >> 5] = s; wq[tid >> 5] = q; }
    __syncthreads();
    if (tid < 8) {
        s = ws[tid]; q = wq[tid];
#pragma unroll
        for (int o = 4; o; o >>= 1) {
            s += __shfl_xor_sync(0xffu, s, o);
            q += __shfl_xor_sync(0xffu, q, o);
        }
        if (tid == 0) {
            atomicAdd(&g_msum[row & 255], s);
            atomicAdd(&g_msq [row & 255], q);
        }
    }
}

__global__ void k_finm() {
    int t = threadIdx.x;
    if (t < Cc) {
        float inv_n = 1.0f / (float)BN;
        float m = g_msum[t] * inv_n;
        float v = g_msq[t] * inv_n - m * m;
        g_mmean[t] = m;
        g_minv[t]  = rsqrtf(v + 1e-5f);
    }
}

__global__ void __launch_bounds__(256) k_bnapply(const float* __restrict__ gm,
                                                 const float* __restrict__ bm,
                                                 float* __restrict__ out) {
    size_t i4 = (size_t)blockIdx.x * 256 + threadIdx.x;
    size_t i = i4 * 4;
    int d = (int)((i >> 14) & 255u);
    float mean = g_mmean[d], inv = g_minv[d], ga = gm[d], be = bm[d];
    float4 v = *(const float4*)&g_mpre[i];
    v.x = gelu_t((v.x - mean) * inv * ga + be);
    v.y = gelu_t((v.y - mean) * inv * ga + be);
    v.z = gelu_t((v.z - mean) * inv * ga + be);
    v.w = gelu_t((v.w - mean) * inv * ga + be);
    *(float4*)&out[OFS_M + i] = v;
}

__global__ void k_ballq(const float* __restrict__ points, float* __restrict__ out) {
    int gid = blockIdx.x * blockDim.x + threadIdx.x;
    int w = gid >> 5, lane = gid & 31;
    if (w >= Bb * Kq) return;
    int b = w >> 8;
    float qx = g_qx[w], qy = g_qy[w], qz = g_qz[w];
    const float* px = points + (size_t)b * 3 * Nn;
    const float* py = px + Nn;
    const float* pz = px + 2 * Nn;
    float* o0 = out + OFS_G0 + (size_t)w * 32;
    float* o1 = out + OFS_G1 + (size_t)w * 64;
    int cnt0 = 0, cnt1 = 0, first0 = -1, first1 = -1;
    const float r0sq = 0.04f, r1sq = 0.16f;

    for (int base = 0; base < Nn; base += 32) {
        int n = base + lane;
        float dx = __fadd_rn(px[n], -qx);
        float dy = __fadd_rn(py[n], -qy);
        float dz = __fadd_rn(pz[n], -qz);
        float d2 = __fadd_rn(__fadd_rn(__fmul_rn(dx, dx), __fmul_rn(dy, dy)),
                             __fmul_rn(dz, dz));
        bool in1 = (d2 <= r1sq);
        bool in0 = (d2 <= r0sq);
        unsigned m1 = __ballot_sync(0xffffffffu, in1);
        unsigned m0 = __ballot_sync(0xffffffffu, in0);
        if (m1) {
            if (first1 < 0) first1 = base + __ffs(m1) - 1;
            if (cnt1 < 64) {
                if (in1) {
                    int slot = cnt1 + __popc(m1 & ((1u << lane) - 1u));
                    if (slot < 64) o1[slot] = (float)n;
                }
                cnt1 += __popc(m1);
                if (cnt1 > 64) cnt1 = 64;
            }
        }
        if (m0) {
            if (first0 < 0) first0 = base + __ffs(m0) - 1;
            if (cnt0 < 32) {
                if (in0) {
                    int slot = cnt0 + __popc(m0 & ((1u << lane) - 1u));
                    if (slot < 32) o0[slot] = (float)n;
                }
                cnt0 += __popc(m0);
                if (cnt0 > 32) cnt0 = 32;
            }
        }
        if (cnt0 >= 32 && cnt1 >= 64) break;
    }
    if (first1 < 0) first1 = Nn - 1;
    if (first0 < 0) first0 = Nn - 1;
    for (int s = cnt1 + lane; s < 64; s += 32) o1[s] = (float)first1;
    for (int s = cnt0 + lane; s < 32; s += 32) o0[s] = (float)first0;
}

// ------------------- host -------------------
extern "C" void kernel_launch(void* const* d_in, const int* in_sizes, int n_in,
                              void* d_out, int out_size) {
    const float* points = (const float*)d_in[0];
    const float* feats  = (const float*)d_in[1];
    const float* w1     = (const float*)d_in[2];
    const float* g1     = (const float*)d_in[3];
    const float* b1     = (const float*)d_in[4];
    const float* w2     = (const float*)d_in[5];
    const float* wm     = (const float*)d_in[6];
    const float* gm     = (const float*)d_in[7];
    const float* bm     = (const float*)d_in[8];
    float* out = (float*)d_out;

    cudaFuncSetAttribute(k_select, cudaFuncAttributeMaxDynamicSharedMemorySize,
                         2 * Nn * (int)sizeof(uint32_t));

    k_reset<<<1, 256>>>();
    k_prep_wm<<<64, 256>>>(wm);
    k_gemm_h<<<dim3(Nn / 128, Bb), 256>>>(feats, w1);
    k_finh<<<1, 64>>>();
    k_heat<<<BN / 128, 128>>>(g1, b1, w2);
    k_finpred<<<1, 64>>>(out);
    k_select<<<Bb, 256, 2 * Nn * sizeof(uint32_t)>>>(points, out);
    k_qfeats<<<Bb * Cc, Kq>>>(feats, out);
    k_gemm_m<<<dim3(Nn / 128, 2, Bb), 256>>>(feats);
    k_mstats<<<Bb * Cc, 256>>>();
    k_finm<<<1, 256>>>();
    k_bnapply<<<(size_t)Bb * Cc * Nn / (256 * 4), 256>>>(gm, bm, out);
    k_ballq<<<(Bb * Kq * 32) / 128, 128>>>(points, out);
}

// round 12
// speedup vs baseline: 1.2135x; 1.0267x over previous
#include <cuda_runtime.h>
#include <cuda_bf16.h>
#include <stdint.h>

#define Bb 4
#define Cc 256
#define Nn 16384
#define Hh 64
#define Ss 10
#define Kq 256
#define BN (Bb*Nn)

// Output layout (float32, concatenated in tuple order)
#define OFS_Q     0u
#define OFS_QF    3072u
#define OFS_PRED  265216u
#define OFS_M     265256u
#define OFS_G0    17042472u
#define OFS_G1    17075240u

// ------------------- device scratch (allocation-free) -------------------
__device__ float g_P[(size_t)Hh*BN];          // transposed: [h][row]
__device__ float g_hm[(size_t)Bb*Nn*Ss];
__device__ float g_mpre[(size_t)Bb*Cc*Nn];    // 67 MB
__device__ float g_hsum[Hh], g_hsq[Hh], g_hmean[Hh], g_hinv[Hh];
__device__ float g_pred[Bb*Ss];
__device__ int   g_label[Bb];
__device__ float g_msum[Cc], g_msq[Cc], g_mmean[Cc], g_minv[Cc];
__device__ int   g_qidx[Bb*Kq];
__device__ float g_qx[Bb*Kq], g_qy[Bb*Kq], g_qz[Bb*Kq];
// wm^T bf16 hi/lo, plain row-major [d][c]
__device__ __nv_bfloat16 g_wmTh[Cc*Cc];
__device__ __nv_bfloat16 g_wmTl[Cc*Cc];

__device__ __forceinline__ float gelu_t(float x) {
    float x3 = x * x * x;
    float t = tanhf(0.7978845608028654f * (x + 0.044715f * x3));
    return 0.5f * x * (1.0f + t);
}
__device__ __forceinline__ uint32_t f2ord(float f) {
    uint32_t u = __float_as_uint(f);
    return (u & 0x80000000u) ? ~u : (u | 0x80000000u);
}
__device__ __forceinline__ uint32_t smem_u32(const void* p) {
    uint32_t a;
    asm("{ .reg .u64 t; cvta.to.shared.u64 t, %1; cvt.u32.u64 %0, t; }"
        : "=r"(a) : "l"(p));
    return a;
}
__device__ __forceinline__ void ldsm_x4(uint32_t* r, uint32_t addr) {
    asm volatile("ldmatrix.sync.aligned.m8n8.x4.shared.b16 {%0,%1,%2,%3}, [%4];"
                 : "=r"(r[0]), "=r"(r[1]), "=r"(r[2]), "=r"(r[3]) : "r"(addr));
}
__device__ __forceinline__ void ldsm_x4t(uint32_t* r, uint32_t addr) {
    asm volatile("ldmatrix.sync.aligned.m8n8.x4.trans.shared.b16 {%0,%1,%2,%3}, [%4];"
                 : "=r"(r[0]), "=r"(r[1]), "=r"(r[2]), "=r"(r[3]) : "r"(addr));
}
__device__ __forceinline__ void mma16816(float* d, const uint32_t* a, const uint32_t* b) {
    asm volatile(
        "mma.sync.aligned.m16n8k16.row.col.f32.bf16.bf16.f32 "
        "{%0,%1,%2,%3}, {%4,%5,%6,%7}, {%8,%9}, {%0,%1,%2,%3};"
        : "+f"(d[0]), "+f"(d[1]), "+f"(d[2]), "+f"(d[3])
        : "r"(a[0]), "r"(a[1]), "r"(a[2]), "r"(a[3]), "r"(b[0]), "r"(b[1]));
}

// ------------------- kernels -------------------

__global__ void k_reset() {
    int t = threadIdx.x;
    if (t < Hh)      { g_hsum[t] = 0.0f; g_hsq[t] = 0.0f; }
    if (t < Bb * Ss) { g_pred[t] = 0.0f; }
    if (t < Cc)      { g_msum[t] = 0.0f; g_msq[t] = 0.0f; }
}

// g_wmT[d][c] = wm[c][d], bf16 hi/lo split
__global__ void k_prep_wm(const float* __restrict__ wm) {
    int idx = blockIdx.x * blockDim.x + threadIdx.x;
    for (int i = idx; i < Cc * Cc; i += gridDim.x * blockDim.x) {
        int d = i >> 8, c = i & 255;
        float v = wm[(size_t)c * Cc + d];
        __nv_bfloat16 hi = __float2bfloat16(v);
        __nv_bfloat16 lo = __float2bfloat16(__fsub_rn(v, __bfloat162float(hi)));
        g_wmTh[i] = hi;
        g_wmTl[i] = lo;
    }
}

// P^T = (x @ w1)^T stored [h][row].  Epilogue: per-column sum/sumsq.
__global__ void __launch_bounds__(256) k_gemm_h(const float* __restrict__ feats,
                                                const float* __restrict__ w1) {
    __shared__ float As[32][128];
    __shared__ float Ws[32][64];
    __shared__ float csum[64], csq[64];
    int b = blockIdx.y;
    int n0 = blockIdx.x * 128;
    int tid = threadIdx.x, ty = tid >> 4, tx = tid & 15;
    const float* fb = feats + (size_t)b * Cc * Nn;

    float acc[8][4];
#pragma unroll
    for (int r = 0; r < 8; r++)
#pragma unroll
        for (int c = 0; c < 4; c++) acc[r][c] = 0.0f;

    for (int k0 = 0; k0 < Cc; k0 += 32) {
#pragma unroll
        for (int i = 0; i < 4; i++) {
            int t = tid + i * 256; int rw = t >> 5; int c4 = t & 31;
            *(float4*)&As[rw][c4 * 4] =
                *(const float4*)&fb[(size_t)(k0 + rw) * Nn + n0 + c4 * 4];
        }
#pragma unroll
        for (int i = 0; i < 2; i++) {
            int t = tid + i * 256; int rw = t >> 4; int c4 = t & 15;
            *(float4*)&Ws[rw][c4 * 4] =
                *(const float4*)&w1[(size_t)(k0 + rw) * Hh + c4 * 4];
        }
        __syncthreads();
#pragma unroll
        for (int kk = 0; kk < 32; kk++) {
            float4 a0 = *(float4*)&As[kk][ty * 8];
            float4 a1 = *(float4*)&As[kk][ty * 8 + 4];
            float4 bb = *(float4*)&Ws[kk][tx * 4];
            float ar[8] = {a0.x, a0.y, a0.z, a0.w, a1.x, a1.y, a1.z, a1.w};
            float br[4] = {bb.x, bb.y, bb.z, bb.w};
#pragma unroll
            for (int r = 0; r < 8; r++)
#pragma unroll
                for (int c = 0; c < 4; c++) acc[r][c] += ar[r] * br[c];
        }
        __syncthreads();
    }

    if (tid < 64) { csum[tid] = 0.0f; csq[tid] = 0.0f; }
    __syncthreads();

    size_t rowbase = (size_t)b * Nn + n0 + ty * 8;
#pragma unroll
    for (int c = 0; c < 4; c++) {
        int h = tx * 4 + c;
        *(float4*)&g_P[(size_t)h * BN + rowbase] =
            make_float4(acc[0][c], acc[1][c], acc[2][c], acc[3][c]);
        *(float4*)&g_P[(size_t)h * BN + rowbase + 4] =
            make_float4(acc[4][c], acc[5][c], acc[6][c], acc[7][c]);
        float s = 0.0f, q = 0.0f;
#pragma unroll
        for (int r = 0; r < 8; r++) { s += acc[r][c]; q += acc[r][c] * acc[r][c]; }
        atomicAdd(&csum[h], s);
        atomicAdd(&csq [h], q);
    }
    __syncthreads();
    if (tid < 64) {
        atomicAdd(&g_hsum[tid], csum[tid]);
        atomicAdd(&g_hsq [tid], csq [tid]);
    }
}

__global__ void k_finh() {
    int t = threadIdx.x;
    if (t < Hh) {
        float inv_n = 1.0f / (float)BN;
        float m = g_hsum[t] * inv_n;
        float v = g_hsq[t] * inv_n - m * m;
        g_hmean[t] = m;
        g_hinv[t]  = rsqrtf(v + 1e-5f);
    }
}

// heatmap from transposed P: coalesced column reads
__global__ void __launch_bounds__(128) k_heat(const float* __restrict__ g1,
                                              const float* __restrict__ b1,
                                              const float* __restrict__ w2) {
    __shared__ float w2s[Hh * Ss];
    __shared__ float smn[Hh], siv[Hh], sga[Hh], sbe[Hh];
    __shared__ float sp[Ss];
    int tid = threadIdx.x;
    if (tid < Hh) {
        smn[tid] = g_hmean[tid]; siv[tid] = g_hinv[tid];
        sga[tid] = g1[tid];      sbe[tid] = b1[tid];
    }
    for (int i = tid; i < Hh * Ss; i += 128) w2s[i] = w2[i];
    if (tid < Ss) sp[tid] = 0.0f;
    __syncthreads();

    int r = blockIdx.x * 128 + tid;
    int b = r >> 14;
    float o[Ss];
#pragma unroll
    for (int s = 0; s < Ss; s++) o[s] = 0.0f;
#pragma unroll 8
    for (int j = 0; j < Hh; j++) {
        float p = g_P[(size_t)j * BN + r];
        float h = gelu_t((p - smn[j]) * siv[j] * sga[j] + sbe[j]);
#pragma unroll
        for (int s = 0; s < Ss; s++) o[s] += h * w2s[j * Ss + s];
    }
#pragma unroll
    for (int s = 0; s < Ss; s++) {
        g_hm[(size_t)r * Ss + s] = o[s];
        atomicAdd(&sp[s], o[s]);
    }
    __syncthreads();
    if (tid < Ss) atomicAdd(&g_pred[b * Ss + tid], sp[tid]);
}

__global__ void k_finpred(float* __restrict__ out) {
    __shared__ float p[Bb * Ss];
    int t = threadIdx.x;
    if (t < Bb * Ss) {
        float v = g_pred[t] * (1.0f / (float)Nn);
        p[t] = v;
        out[OFS_PRED + t] = v;
    }
    __syncthreads();
    if (t < Bb) {
        int best = 0; float bv = p[t * Ss];
        for (int s = 1; s < Ss; s++) {
            float v = p[t * Ss + s];
            if (v > bv) { bv = v; best = s; }
        }
        g_label[t] = best;
    }
}

// Exact top-256 by (value desc, index asc): radix select + bitonic sort.
__global__ void __launch_bounds__(256) k_select(const float* __restrict__ points,
                                                float* __restrict__ out) {
    extern __shared__ uint32_t dyn[];
    uint32_t* u   = dyn;
    uint32_t* tie = dyn + Nn;
    __shared__ uint32_t hist[256];
    __shared__ unsigned long long sel[256];
    __shared__ uint32_t s_prefix, s_rem, s_cntG, s_cntE;

    int tid = threadIdx.x;
    int b = blockIdx.x;
    int lab = g_label[b];

    for (int n = tid; n < Nn; n += 256)
        u[n] = f2ord(g_hm[((size_t)(b * Nn + n)) * Ss + lab]);
    if (tid == 0) { s_prefix = 0u; s_rem = Kq; }
    __syncthreads();

    for (int shift = 24; shift >= 0; shift -= 8) {
        hist[tid] = 0u;
        __syncthreads();
        uint32_t pref = s_prefix;
        for (int n = tid; n < Nn; n += 256) {
            uint32_t uu = u[n];
            bool ok = (shift == 24) || ((uu >> (shift + 8)) == (pref >> (shift + 8)));
            if (ok) atomicAdd(&hist[(uu >> shift) & 255u], 1u);
        }
        __syncthreads();
        if (tid == 0) {
            uint32_t acc = 0, rem = s_rem; int chosen = 0;
            for (int bin = 255; bin >= 0; --bin) {
                uint32_t c = hist[bin];
                if (acc + c >= rem) { chosen = bin; break; }
                acc += c;
            }
            s_rem = rem - acc;
            s_prefix = pref | ((uint32_t)chosen << shift);
        }
        __syncthreads();
    }

    uint32_t T = s_prefix;
    uint32_t need = s_rem;
    if (tid == 0) { s_cntG = 0u; s_cntE = 0u; }
    __syncthreads();
    for (int n = tid; n < Nn; n += 256) {
        uint32_t uu = u[n];
        if (uu > T) {
            uint32_t p = atomicAdd(&s_cntG, 1u);
            sel[p] = (((unsigned long long)(~uu)) << 32) | (uint32_t)n;
        } else if (uu == T) {
            uint32_t p = atomicAdd(&s_cntE, 1u);
            tie[p] = (uint32_t)n;
        }
    }
    __syncthreads();
    uint32_t cG = s_cntG, cE = s_cntE;

    if (cE > need) {
        for (int i = tid; i < Nn; i += 256)
            if (i >= (int)cE) tie[i] = 0xFFFFFFFFu;
        __syncthreads();
        for (int k = 2; k <= Nn; k <<= 1)
            for (int j = k >> 1; j > 0; j >>= 1) {
                for (int i = tid; i < Nn; i += 256) {
                    int ixj = i ^ j;
                    if (ixj > i) {
                        uint32_t a = tie[i], c = tie[ixj];
                        bool up = ((i & k) == 0);
                        if ((a > c) == up) { tie[i] = c; tie[ixj] = a; }
                    }
                }
                __syncthreads();
            }
    }
    for (uint32_t i = tid; i < need; i += 256)
        sel[cG + i] = (((unsigned long long)(~T)) << 32) | tie[i];
    __syncthreads();

    for (int k = 2; k <= 256; k <<= 1)
        for (int j = k >> 1; j > 0; j >>= 1) {
            int i = tid, ixj = i ^ j;
            if (ixj > i) {
                unsigned long long a = sel[i], c = sel[ixj];
                bool up = ((i & k) == 0);
                if ((a > c) == up) { sel[i] = c; sel[ixj] = a; }
            }
            __syncthreads();
        }

    int k = tid;
    uint32_t idx = (uint32_t)(sel[k] & 0xFFFFFFFFu);
    g_qidx[b * Kq + k] = (int)idx;
    const float* pb = points + (size_t)b * 3 * Nn;
    float px = pb[idx], py = pb[Nn + idx], pz = pb[2 * Nn + idx];
    out[OFS_Q + (size_t)b * 768 + k]       = px;
    out[OFS_Q + (size_t)b * 768 + 256 + k] = py;
    out[OFS_Q + (size_t)b * 768 + 512 + k] = pz;
    g_qx[b * Kq + k] = px; g_qy[b * Kq + k] = py; g_qz[b * Kq + k] = pz;
}

__global__ void k_qfeats(const float* __restrict__ feats, float* __restrict__ out) {
    int bid = blockIdx.x;
    int b = bid >> 8, c = bid & 255, k = threadIdx.x;
    int idx = g_qidx[b * Kq + k];
    out[OFS_QF + ((size_t)(b * Cc + c)) * Kq + k] =
        __ldg(&feats[(size_t)b * Cc * Nn + (size_t)c * Nn + idx]);
}

// ---------- m-GEMM v2: one CTA computes ALL 256 d for a 128-n tile ----------
// D[d][n] = sum_c wmT[d][c] * feats[b][c][n], 3-product bf16 split.
// 8 warps: dgrp = wid>>1 (4 x 64d), ngrp = wid&1 (2 x 64n). acc[4][8][4].
// Epilogue fuses per-d sum/sumsq into g_msum/g_msq (k_mstats deleted).
#define A_STR 40
#define B_STR 136
#define AH_OFF 0
#define AL_OFF 20480
#define BH_OFF 40960
#define BL_OFF 49664
#define GM_SMEM 58368
__global__ void __launch_bounds__(256, 1) k_gemm_m(const float* __restrict__ feats) {
    extern __shared__ char sm[];
    __nv_bfloat16* sAh = (__nv_bfloat16*)(sm + AH_OFF);   // [256][A_STR]
    __nv_bfloat16* sAl = (__nv_bfloat16*)(sm + AL_OFF);
    __nv_bfloat16* sBh = (__nv_bfloat16*)(sm + BH_OFF);   // [32][B_STR]
    __nv_bfloat16* sBl = (__nv_bfloat16*)(sm + BL_OFF);

    int tid = threadIdx.x;
    int wid = tid >> 5, lane = tid & 31;
    int b  = blockIdx.y;
    int n0 = blockIdx.x * 128;
    int dw = (wid >> 1) * 64;
    int nw = (wid & 1) * 64;
    int lrow = lane & 15, lhi = lane >> 4;
    const float* fb = feats + (size_t)b * Cc * Nn;

    uint32_t aHiB = smem_u32(sAh), aLoB = smem_u32(sAl);
    uint32_t bHiB = smem_u32(sBh), bLoB = smem_u32(sBl);

    float acc[4][8][4];
#pragma unroll
    for (int mt = 0; mt < 4; mt++)
#pragma unroll
        for (int nt = 0; nt < 8; nt++)
#pragma unroll
            for (int r = 0; r < 4; r++) acc[mt][nt][r] = 0.0f;

    const uint32_t* wh = (const uint32_t*)g_wmTh;
    const uint32_t* wl = (const uint32_t*)g_wmTl;
    uint32_t* sAhu = (uint32_t*)sAh;
    uint32_t* sAlu = (uint32_t*)sAl;
    uint32_t* sBhu = (uint32_t*)sBh;
    uint32_t* sBlu = (uint32_t*)sBl;

    for (int kc = 0; kc < 8; kc++) {
        __syncthreads();
        // A: wmT[0..256][kc*32..+32] hi/lo
#pragma unroll
        for (int i = tid; i < 4096; i += 256) {
            int row = i >> 4, cp = i & 15;
            int gi = row * (Cc / 2) + kc * 16 + cp;
            sAhu[row * (A_STR / 2) + cp] = wh[gi];
            sAlu[row * (A_STR / 2) + cp] = wl[gi];
        }
        // B: feats[kc*32..+32][n0..+128] -> bf16 hi/lo
#pragma unroll
        for (int i = tid; i < 2048; i += 256) {
            int crow = i >> 6, np = i & 63;
            float2 f2 = *(const float2*)&fb[(size_t)(kc * 32 + crow) * Nn + n0 + 2 * np];
            __nv_bfloat16 h0 = __float2bfloat16(f2.x);
            __nv_bfloat16 h1 = __float2bfloat16(f2.y);
            __nv_bfloat16 l0 = __float2bfloat16(__fsub_rn(f2.x, __bfloat162float(h0)));
            __nv_bfloat16 l1 = __float2bfloat16(__fsub_rn(f2.y, __bfloat162float(h1)));
            sBhu[crow * (B_STR / 2) + np] =
                ((uint32_t)__bfloat16_as_ushort(h1) << 16) | __bfloat16_as_ushort(h0);
            sBlu[crow * (B_STR / 2) + np] =
                ((uint32_t)__bfloat16_as_ushort(l1) << 16) | __bfloat16_as_ushort(l0);
        }
        __syncthreads();

#pragma unroll
        for (int ks = 0; ks < 2; ks++) {
            uint32_t Afh[4][4], Afl[4][4], Bfh[4][4], Bfl[4][4];
#pragma unroll
            for (int mt = 0; mt < 4; mt++) {
                uint32_t aoff = (uint32_t)((dw + mt * 16 + lrow) * (A_STR * 2) +
                                           ks * 32 + lhi * 16);
                ldsm_x4(Afh[mt], aHiB + aoff);
                ldsm_x4(Afl[mt], aLoB + aoff);
            }
#pragma unroll
            for (int np = 0; np < 4; np++) {
                uint32_t boff = (uint32_t)((ks * 16 + lrow) * (B_STR * 2) +
                                           (nw + np * 16) * 2 + lhi * 16);
                ldsm_x4t(Bfh[np], bHiB + boff);
                ldsm_x4t(Bfl[np], bLoB + boff);
            }
#pragma unroll
            for (int mt = 0; mt < 4; mt++)
#pragma unroll
                for (int nt = 0; nt < 8; nt++) {
                    const uint32_t* bh = &Bfh[nt >> 1][(nt & 1) * 2];
                    const uint32_t* bl = &Bfl[nt >> 1][(nt & 1) * 2];
                    mma16816(acc[mt][nt], Afh[mt], bh);
                    mma16816(acc[mt][nt], Afh[mt], bl);
                    mma16816(acc[mt][nt], Afl[mt], bh);
                }
        }
    }

    // epilogue: store D + fused per-d stats
    __syncthreads();
    float* ssum = (float*)(sm + BH_OFF);          // reuse B smem: [256]
    float* ssq  = (float*)(sm + BH_OFF + 1024);   // [256]
    if (tid < 256) { ssum[tid] = 0.0f; ssq[tid] = 0.0f; }
    __syncthreads();

    int tg = lane & 3, g = lane >> 2;
#pragma unroll
    for (int mt = 0; mt < 4; mt++) {
        int drg  = dw + mt * 16 + g;
        float s0 = 0.0f, q0 = 0.0f, s1 = 0.0f, q1 = 0.0f;
#pragma unroll
        for (int nt = 0; nt < 8; nt++) {
            int ncol = n0 + nw + nt * 8 + 2 * tg;
            float a0 = acc[mt][nt][0], a1 = acc[mt][nt][1];
            float a2 = acc[mt][nt][2], a3 = acc[mt][nt][3];
            *(float2*)&g_mpre[((size_t)(b * Cc + drg)) * Nn + ncol] = make_float2(a0, a1);
            *(float2*)&g_mpre[((size_t)(b * Cc + drg + 8)) * Nn + ncol] = make_float2(a2, a3);
            s0 += a0 + a1;  q0 += a0 * a0 + a1 * a1;
            s1 += a2 + a3;  q1 += a2 * a2 + a3 * a3;
        }
        atomicAdd(&ssum[drg], s0);     atomicAdd(&ssq[drg], q0);
        atomicAdd(&ssum[drg + 8], s1); atomicAdd(&ssq[drg + 8], q1);
    }
    __syncthreads();
    if (tid < 256) {
        atomicAdd(&g_msum[tid], ssum[tid]);
        atomicAdd(&g_msq [tid], ssq [tid]);
    }
}

__global__ void k_finm() {
    int t = threadIdx.x;
    if (t < Cc) {
        float inv_n = 1.0f / (float)BN;
        float m = g_msum[t] * inv_n;
        float v = g_msq[t] * inv_n - m * m;
        g_mmean[t] = m;
        g_minv[t]  = rsqrtf(v + 1e-5f);
    }
}

__global__ void __launch_bounds__(256) k_bnapply(const float* __restrict__ gm,
                                                 const float* __restrict__ bm,
                                                 float* __restrict__ out) {
    size_t i4 = (size_t)blockIdx.x * 256 + threadIdx.x;
    size_t i = i4 * 4;
    int d = (int)((i >> 14) & 255u);
    float mean = g_mmean[d], inv = g_minv[d], ga = gm[d], be = bm[d];
    float4 v = *(const float4*)&g_mpre[i];
    v.x = gelu_t((v.x - mean) * inv * ga + be);
    v.y = gelu_t((v.y - mean) * inv * ga + be);
    v.z = gelu_t((v.z - mean) * inv * ga + be);
    v.w = gelu_t((v.w - mean) * inv * ga + be);
    *(float4*)&out[OFS_M + i] = v;
}

__global__ void k_ballq(const float* __restrict__ points, float* __restrict__ out) {
    int gid = blockIdx.x * blockDim.x + threadIdx.x;
    int w = gid >> 5, lane = gid & 31;
    if (w >= Bb * Kq) return;
    int b = w >> 8;
    float qx = g_qx[w], qy = g_qy[w], qz = g_qz[w];
    const float* px = points + (size_t)b * 3 * Nn;
    const float* py = px + Nn;
    const float* pz = px + 2 * Nn;
    float* o0 = out + OFS_G0 + (size_t)w * 32;
    float* o1 = out + OFS_G1 + (size_t)w * 64;
    int cnt0 = 0, cnt1 = 0, first0 = -1, first1 = -1;
    const float r0sq = 0.04f, r1sq = 0.16f;

    for (int base = 0; base < Nn; base += 32) {
        int n = base + lane;
        float dx = __fadd_rn(px[n], -qx);
        float dy = __fadd_rn(py[n], -qy);
        float dz = __fadd_rn(pz[n], -qz);
        float d2 = __fadd_rn(__fadd_rn(__fmul_rn(dx, dx), __fmul_rn(dy, dy)),
                             __fmul_rn(dz, dz));
        bool in1 = (d2 <= r1sq);
        bool in0 = (d2 <= r0sq);
        unsigned m1 = __ballot_sync(0xffffffffu, in1);
        unsigned m0 = __ballot_sync(0xffffffffu, in0);
        if (m1) {
            if (first1 < 0) first1 = base + __ffs(m1) - 1;
            if (cnt1 < 64) {
                if (in1) {
                    int slot = cnt1 + __popc(m1 & ((1u << lane) - 1u));
                    if (slot < 64) o1[slot] = (float)n;
                }
                cnt1 += __popc(m1);
                if (cnt1 > 64) cnt1 = 64;
            }
        }
        if (m0) {
            if (first0 < 0) first0 = base + __ffs(m0) - 1;
            if (cnt0 < 32) {
                if (in0) {
                    int slot = cnt0 + __popc(m0 & ((1u << lane) - 1u));
                    if (slot < 32) o0[slot] = (float)n;
                }
                cnt0 += __popc(m0);
                if (cnt0 > 32) cnt0 = 32;
            }
        }
        if (cnt0 >= 32 && cnt1 >= 64) break;
    }
    if (first1 < 0) first1 = Nn - 1;
    if (first0 < 0) first0 = Nn - 1;
    for (int s = cnt1 + lane; s < 64; s += 32) o1[s] = (float)first1;
    for (int s = cnt0 + lane; s < 32; s += 32) o0[s] = (float)first0;
}

// ------------------- host -------------------
extern "C" void kernel_launch(void* const* d_in, const int* in_sizes, int n_in,
                              void* d_out, int out_size) {
    const float* points = (const float*)d_in[0];
    const float* feats  = (const float*)d_in[1];
    const float* w1     = (const float*)d_in[2];
    const float* g1     = (const float*)d_in[3];
    const float* b1     = (const float*)d_in[4];
    const float* w2     = (const float*)d_in[5];
    const float* wm     = (const float*)d_in[6];
    const float* gm     = (const float*)d_in[7];
    const float* bm     = (const float*)d_in[8];
    float* out = (float*)d_out;

    cudaFuncSetAttribute(k_select, cudaFuncAttributeMaxDynamicSharedMemorySize,
                         2 * Nn * (int)sizeof(uint32_t));
    cudaFuncSetAttribute(k_gemm_m, cudaFuncAttributeMaxDynamicSharedMemorySize,
                         GM_SMEM);

    k_reset<<<1, 256>>>();
    k_prep_wm<<<64, 256>>>(wm);
    k_gemm_h<<<dim3(Nn / 128, Bb), 256>>>(feats, w1);
    k_finh<<<1, 64>>>();
    k_heat<<<BN / 128, 128>>>(g1, b1, w2);
    k_finpred<<<1, 64>>>(out);
    k_select<<<Bb, 256, 2 * Nn * sizeof(uint32_t)>>>(points, out);
    k_qfeats<<<Bb * Cc, Kq>>>(feats, out);
    k_gemm_m<<<dim3(Nn / 128, Bb), 256, GM_SMEM>>>(feats);
    k_finm<<<1, 256>>>();
    k_bnapply<<<(size_t)Bb * Cc * Nn / (256 * 4), 256>>>(gm, bm, out);
    k_ballq<<<(Bb * Kq * 32) / 128, 128>>>(points, out);
}